// round 17
// baseline (speedup 1.0000x reference)
#include <cuda_runtime.h>
#include <cuda_bf16.h>
#include <math.h>
#include <stdint.h>
#include <string.h>

#define B_   256
#define T_   512
#define IN_  128
#define H_   256
#define G3_  768          // 3*H
#define BT_  (B_ * T_)    // 131072
#define OUT_ 128
#define EPS_ 1e-5f

// ---------------- device-global scratch ----------------
__device__ float g_G [(size_t)BT_ * G3_];   // gi for current layer (reused)
__device__ float g_H1[(size_t)BT_ * H_];    // layer-1 hidden seq (b,t,h)
__device__ float g_H2[(size_t)BT_ * H_];    // layer-2 hidden seq (b,t,h)
__device__ float g_part[512 * 512];         // BN partial sums
__device__ float g_bnsum[2 * H_];
__device__ float g_sum[B_ * H_];

// ---------------- activations / helpers ----------------
__device__ __forceinline__ float fexp2a(float x) {
    float y;
    asm("ex2.approx.f32 %0, %1;" : "=f"(y) : "f"(x));
    return y;
}
__device__ __forceinline__ float fsigmoid(float x) {
    return 1.0f / (1.0f + fexp2a(-1.4426950408889634f * x));
}
__device__ __forceinline__ float ftanh(float x) {
    float e = fexp2a(2.8853900817779268f * x);
    return 1.0f - 2.0f / (e + 1.0f);
}
__device__ __forceinline__ uint32_t smem_u32(const void* p) {
    uint32_t a;
    asm("{ .reg .u64 t; cvta.to.shared.u64 t, %1; cvt.u32.u64 %0, t; }" : "=r"(a) : "l"(p));
    return a;
}
__device__ __forceinline__ void ldm_x4(uint32_t a, uint32_t* r) {
    asm volatile("ldmatrix.sync.aligned.m8n8.x4.shared.b16 {%0,%1,%2,%3}, [%4];"
                 : "=r"(r[0]), "=r"(r[1]), "=r"(r[2]), "=r"(r[3]) : "r"(a));
}
__device__ __forceinline__ void ldm_x2(uint32_t a, uint32_t* r) {
    asm volatile("ldmatrix.sync.aligned.m8n8.x2.shared.b16 {%0,%1}, [%2];"
                 : "=r"(r[0]), "=r"(r[1]) : "r"(a));
}
__device__ __forceinline__ void mma16816(float* c, const uint32_t* a, uint32_t b0, uint32_t b1) {
    asm volatile(
        "mma.sync.aligned.m16n8k16.row.col.f32.bf16.bf16.f32 "
        "{%0,%1,%2,%3}, {%4,%5,%6,%7}, {%8,%9}, {%0,%1,%2,%3};"
        : "+f"(c[0]), "+f"(c[1]), "+f"(c[2]), "+f"(c[3])
        : "r"(a[0]), "r"(a[1]), "r"(a[2]), "r"(a[3]), "r"(b0), "r"(b1));
}
__device__ __forceinline__ void cvt_split(float v, __nv_bfloat16& h, __nv_bfloat16& l) {
    h = __float2bfloat16(v);
    l = __float2bfloat16(v - __bfloat162float(h));
}
__device__ __forceinline__ uint16_t bfbits(__nv_bfloat16 b) {
    uint16_t u; memcpy(&u, &b, 2); return u;
}

// ---------------- split-bf16 tensor-core GEMM (unchanged, verified) ----------------
#define WSTR 40   // bf16 elems per row (80 B)

template <int K, int SRC>
__global__ __launch_bounds__(256) void k_mma(const float* __restrict__ Ain,
                                             const float* __restrict__ W,
                                             const float* __restrict__ bias) {
    const float* A = (SRC == 0) ? Ain : (const float*)g_H1;   // device-side binding!

    __shared__ __nv_bfloat16 sAh[128 * WSTR];
    __shared__ __nv_bfloat16 sAl[128 * WSTR];
    __shared__ __nv_bfloat16 sWh[64 * WSTR];
    __shared__ __nv_bfloat16 sWl[64 * WSTR];

    const int tid = threadIdx.x;
    const int lane = tid & 31;
    const int wid = tid >> 5;
    const int wm = wid >> 1;
    const int wn = wid & 1;
    const int n0 = blockIdx.x * 64;
    const int m0 = blockIdx.y * 128;

    float acc[2][4][4];
#pragma unroll
    for (int mi = 0; mi < 2; mi++)
#pragma unroll
        for (int ni = 0; ni < 4; ni++)
#pragma unroll
            for (int e = 0; e < 4; e++) acc[mi][ni][e] = 0.0f;

    const int arow = (lane & 15);
    const int acol = (lane >> 4) * 8;

    for (int k0 = 0; k0 < K; k0 += 32) {
#pragma unroll
        for (int i = 0; i < 4; i++) {
            int lin = tid + i * 256;
            int row = lin >> 3, qc = lin & 7;
            float4 v = *(const float4*)(A + (size_t)(m0 + row) * K + k0 + qc * 4);
            __nv_bfloat16 hx, lx, hy, ly, hz, lz, hw, lw;
            cvt_split(v.x, hx, lx); cvt_split(v.y, hy, ly);
            cvt_split(v.z, hz, lz); cvt_split(v.w, hw, lw);
            __nv_bfloat162 p;
            p.x = hx; p.y = hy; *(__nv_bfloat162*)(sAh + row * WSTR + qc * 4) = p;
            p.x = hz; p.y = hw; *(__nv_bfloat162*)(sAh + row * WSTR + qc * 4 + 2) = p;
            p.x = lx; p.y = ly; *(__nv_bfloat162*)(sAl + row * WSTR + qc * 4) = p;
            p.x = lz; p.y = lw; *(__nv_bfloat162*)(sAl + row * WSTR + qc * 4 + 2) = p;
        }
#pragma unroll
        for (int i = 0; i < 2; i++) {
            int lin = tid + i * 256;
            int row = lin >> 3, qc = lin & 7;
            float4 v = *(const float4*)(W + (size_t)(n0 + row) * K + k0 + qc * 4);
            __nv_bfloat16 hx, lx, hy, ly, hz, lz, hw, lw;
            cvt_split(v.x, hx, lx); cvt_split(v.y, hy, ly);
            cvt_split(v.z, hz, lz); cvt_split(v.w, hw, lw);
            __nv_bfloat162 p;
            p.x = hx; p.y = hy; *(__nv_bfloat162*)(sWh + row * WSTR + qc * 4) = p;
            p.x = hz; p.y = hw; *(__nv_bfloat162*)(sWh + row * WSTR + qc * 4 + 2) = p;
            p.x = lx; p.y = ly; *(__nv_bfloat162*)(sWl + row * WSTR + qc * 4) = p;
            p.x = lz; p.y = lw; *(__nv_bfloat162*)(sWl + row * WSTR + qc * 4 + 2) = p;
        }
        __syncthreads();

#pragma unroll
        for (int ks = 0; ks < 2; ks++) {
            const int kk = ks * 16;
            uint32_t ah[2][4], al[2][4], bh[2][4], bl[2][4];
#pragma unroll
            for (int mi = 0; mi < 2; mi++) {
                int r = wm * 32 + mi * 16 + arow;
                ldm_x4(smem_u32(sAh + r * WSTR + kk + acol), ah[mi]);
                ldm_x4(smem_u32(sAl + r * WSTR + kk + acol), al[mi]);
            }
#pragma unroll
            for (int ng = 0; ng < 2; ng++) {
                int r = wn * 32 + ng * 16 + arow;
                ldm_x4(smem_u32(sWh + r * WSTR + kk + acol), bh[ng]);
                ldm_x4(smem_u32(sWl + r * WSTR + kk + acol), bl[ng]);
            }
#pragma unroll
            for (int mi = 0; mi < 2; mi++)
#pragma unroll
                for (int ng = 0; ng < 2; ng++)
#pragma unroll
                    for (int s = 0; s < 2; s++) {
                        int ni = 2 * ng + s;
                        mma16816(acc[mi][ni], ah[mi], bh[ng][s], bh[ng][s + 2]);
                        mma16816(acc[mi][ni], ah[mi], bl[ng][s], bl[ng][s + 2]);
                        mma16816(acc[mi][ni], al[mi], bh[ng][s], bh[ng][s + 2]);
                    }
        }
        __syncthreads();
    }

#pragma unroll
    for (int mi = 0; mi < 2; mi++)
#pragma unroll
        for (int ni = 0; ni < 4; ni++) {
            int m = m0 + wm * 32 + mi * 16 + (lane >> 2);
            int n = n0 + wn * 32 + ni * 8 + (lane & 3) * 2;
            float b0 = bias[n], b1 = bias[n + 1];
            float2 v0 = make_float2(acc[mi][ni][0] + b0, acc[mi][ni][1] + b1);
            float2 v1 = make_float2(acc[mi][ni][2] + b0, acc[mi][ni][3] + b1);
            *(float2*)(g_G + (size_t)m * G3_ + n) = v0;
            *(float2*)(g_G + (size_t)(m + 8) * G3_ + n) = v1;
        }
}

// ---------------- tensor-core GRU recurrence: cluster + DSMEM, k-split 16 warps ----------------
// grid (16 batch-groups, 4 feature-CTAs), cluster (1,4,1), 512 thr (16 warps).
// Per step: gh[16x192] = h[16x256] @ Wslice[192x256]^T (split-bf16 mma.sync).
// k-SPLIT: warps 0-7 do k=0..127 over rows 24w; warps 8-15 do k=128..255 (same rows).
// Partials combined deterministically: lo-warps st, barrier, hi-warps red.shared.add.
// XOR-swizzled 512B rows; double-buffered A staging; ONE cluster.sync per step.
#define ROFF_WH 0                             // 192*512 = 98304
#define ROFF_WL 98304
#define ROFF_A  196608                        // A[p]: p*16384; hi +0 (8192), lo +8192
#define GHS 196                               // gh row stride (floats), conflict-padded
#define SMEM_REC (196608 + 2 * 16384)         // 229376

template <int LAYER>
__global__ __launch_bounds__(512) __cluster_dims__(1, 4, 1)
void k_recur(const float* __restrict__ whh, const float* __restrict__ bhh) {
    extern __shared__ char sm8[];
    float* Hbuf = (LAYER == 1) ? g_H1 : g_H2;

    const int tid = threadIdx.x, lane = tid & 31, wid = tid >> 5;
    const int bg = blockIdx.x;
    const int j0 = blockIdx.y * 64;
    const int bb0 = bg * 16;
    const uint32_t sb = smem_u32(sm8);

    // ---- stage W slice once: rows n = 3*f_local + gate, fp32 -> split bf16, swizzled ----
    for (int lin = tid; lin < 192 * 64; lin += 512) {
        int n = lin >> 6, q = lin & 63;                 // q: 4-float granule
        int f = n / 3, gate = n - 3 * f;
        float4 v = *(const float4*)(whh + (size_t)(gate * H_ + j0 + f) * H_ + 4 * q);
        __nv_bfloat16 hx, lx, hy, ly, hz, lz, hw, lw;
        cvt_split(v.x, hx, lx); cvt_split(v.y, hy, ly);
        cvt_split(v.z, hz, lz); cvt_split(v.w, hw, lw);
        uint32_t addr = (uint32_t)(n * 512 + (((q >> 1) ^ (n & 7)) << 4) + (q & 1) * 8);
        __nv_bfloat162 p;
        p.x = hx; p.y = hy; *(__nv_bfloat162*)(sm8 + ROFF_WH + addr) = p;
        p.x = hz; p.y = hw; *(__nv_bfloat162*)(sm8 + ROFF_WH + addr + 4) = p;
        p.x = lx; p.y = ly; *(__nv_bfloat162*)(sm8 + ROFF_WL + addr) = p;
        p.x = lz; p.y = lw; *(__nv_bfloat162*)(sm8 + ROFF_WL + addr + 4) = p;
    }

    // MMA roles: k-split warp groups
    const int klo = (wid < 8) ? 1 : 0;
    const int w8 = wid & 7;
    const int nb = 24 * w8;                             // warp's first W row
    const int kc0 = klo ? 0 : 8;                        // k-chunk base
    const int arow = lane & 15, acol = (lane >> 4) * 8;
    const int xrow = nb + 16 + (lane & 7);
    const int xcol = ((lane >> 3) & 1) * 8;

    // recombine roles: thread = (feature pair, batch)
    const int f0 = 2 * (tid & 31);                      // local feature pair base
    const int blr = tid >> 5;                           // batch 0..15
    const int jg = j0 + f0;
    const float2 br2 = *(const float2*)(bhh + jg);
    const float2 bz2 = *(const float2*)(bhh + 256 + jg);
    const float2 bn2 = *(const float2*)(bhh + 512 + jg);

    // DSMEM peer bases for the A region
    uint32_t dA[4];
#pragma unroll
    for (int r = 0; r < 4; r++)
        asm("mapa.shared::cluster.u32 %0, %1, %2;" : "=r"(dA[r]) : "r"(sb + ROFF_A), "r"(r));

    float hprev[2] = {0.f, 0.f};                        // fp32 recurrent state (this b, f-pair)

    __syncthreads();

    for (int t = 0; t < T_; t++) {
        const int p = t & 1;
        const uint32_t abase = sb + ROFF_A + (uint32_t)p * 16384;
        float* gh = (float*)(sm8 + ROFF_A + p * 16384);
        const uint32_t ghb = abase;                     // gh smem base (u32) for red.add
        const uint32_t pn_off = (uint32_t)((p ^ 1) * 16384);

        // ---- prefetch gi (DRAM) ----
        const float* gp = g_G + ((size_t)(bb0 + blr) * T_ + t) * G3_ + jg;
        float2 gir = *(const float2*)(gp);
        float2 giz = *(const float2*)(gp + 256);
        float2 gin = *(const float2*)(gp + 512);

        if (t > 0) {
            // ---- MMA over this warp-group's k half ----
            float acc[3][4];
#pragma unroll
            for (int ti = 0; ti < 3; ti++)
#pragma unroll
                for (int k = 0; k < 4; k++) acc[ti][k] = 0.0f;

#pragma unroll
            for (int kci = 0; kci < 8; kci++) {
                const int kc = kc0 + kci;
                const int cbyte = kc * 32 + acol * 2;
                const int xbyte = kc * 32 + xcol * 2;
                uint32_t ah[4], al[4], wh4[4], wl4[4], wh2[2], wl2[2];
                uint32_t aoff = (uint32_t)(arow * 512 +
                                ((((cbyte >> 4) ^ (arow & 7))) << 4));
                ldm_x4(abase + aoff, ah);
                ldm_x4(abase + 8192 + aoff, al);
                int wr = nb + arow;
                uint32_t woff = (uint32_t)(wr * 512 +
                                ((((cbyte >> 4) ^ (wr & 7))) << 4));
                ldm_x4(sb + ROFF_WH + woff, wh4);
                ldm_x4(sb + ROFF_WL + woff, wl4);
                uint32_t xoff = (uint32_t)(xrow * 512 +
                                ((((xbyte >> 4) ^ (xrow & 7))) << 4));
                ldm_x2(sb + ROFF_WH + xoff, wh2);
                ldm_x2(sb + ROFF_WL + xoff, wl2);
                mma16816(acc[0], ah, wh4[0], wh4[2]);
                mma16816(acc[0], ah, wl4[0], wl4[2]);
                mma16816(acc[0], al, wh4[0], wh4[2]);
                mma16816(acc[1], ah, wh4[1], wh4[3]);
                mma16816(acc[1], ah, wl4[1], wl4[3]);
                mma16816(acc[1], al, wh4[1], wh4[3]);
                mma16816(acc[2], ah, wh2[0], wh2[1]);
                mma16816(acc[2], ah, wl2[0], wl2[1]);
                mma16816(acc[2], al, wh2[0], wh2[1]);
            }
            __syncthreads();                   // all ldsm of A[p] done (gh aliases it)

            // ---- lo-warps store partials ----
            if (klo) {
#pragma unroll
                for (int ti = 0; ti < 3; ti++) {
                    int col = nb + 8 * ti + 2 * (lane & 3);
                    int r0 = lane >> 2;
                    *(float2*)&gh[r0 * GHS + col] = make_float2(acc[ti][0], acc[ti][1]);
                    *(float2*)&gh[(r0 + 8) * GHS + col] = make_float2(acc[ti][2], acc[ti][3]);
                }
            }
            __syncthreads();
            // ---- hi-warps add partials (deterministic: exactly one st + one add) ----
            if (!klo) {
#pragma unroll
                for (int ti = 0; ti < 3; ti++) {
                    int col = nb + 8 * ti + 2 * (lane & 3);
                    int r0 = lane >> 2;
                    uint32_t a0 = ghb + (uint32_t)(r0 * GHS + col) * 4;
                    uint32_t a1 = ghb + (uint32_t)((r0 + 8) * GHS + col) * 4;
                    asm volatile("red.shared.add.f32 [%0], %1;" :: "r"(a0), "f"(acc[ti][0]) : "memory");
                    asm volatile("red.shared.add.f32 [%0], %1;" :: "r"(a0 + 4), "f"(acc[ti][1]) : "memory");
                    asm volatile("red.shared.add.f32 [%0], %1;" :: "r"(a1), "f"(acc[ti][2]) : "memory");
                    asm volatile("red.shared.add.f32 [%0], %1;" :: "r"(a1 + 4), "f"(acc[ti][3]) : "memory");
                }
            }
            __syncthreads();
        }

        // ---- recombine (all 512 threads: 1 batch x 1 feature-pair) ----
        float h2[2];
#pragma unroll
        for (int cf = 0; cf < 2; cf++) {
            float ghr = 0.f, ghz = 0.f, ghn = 0.f;
            if (t > 0) {
                const float* gq = &gh[blr * GHS + 3 * (f0 + cf)];
                ghr = gq[0]; ghz = gq[1]; ghn = gq[2];
            }
            float gi_r = cf ? gir.y : gir.x;
            float gi_z = cf ? giz.y : giz.x;
            float gi_n = cf ? gin.y : gin.x;
            float b_r = cf ? br2.y : br2.x;
            float b_z = cf ? bz2.y : bz2.x;
            float b_n = cf ? bn2.y : bn2.x;
            float r = fsigmoid(gi_r + ghr + b_r);
            float z = fsigmoid(gi_z + ghz + b_z);
            float n = ftanh(gi_n + r * (ghn + b_n));
            float h = (1.0f - z) * n + z * hprev[cf];
            hprev[cf] = h;
            h2[cf] = h;
        }
        // global H store (float2, coalesced)
        *(float2*)(Hbuf + ((size_t)(bb0 + blr) * T_ + t) * H_ + jg) =
            make_float2(h2[0], h2[1]);
        // pack hi/lo pairs, DSMEM-broadcast into all ranks' A[p^1]
        {
            __nv_bfloat16 h0h, h0l, h1h, h1l;
            cvt_split(h2[0], h0h, h0l);
            cvt_split(h2[1], h1h, h1l);
            uint32_t hi = (uint32_t)bfbits(h0h) | ((uint32_t)bfbits(h1h) << 16);
            uint32_t lo = (uint32_t)bfbits(h0l) | ((uint32_t)bfbits(h1l) << 16);
            uint32_t off = pn_off + (uint32_t)(blr * 512 +
                           (((jg >> 3) ^ (blr & 7)) << 4) + ((f0 & 7) << 1));
#pragma unroll
            for (int r = 0; r < 4; r++) {
                asm volatile("st.shared::cluster.u32 [%0], %1;"
                             :: "r"(dA[r] + off), "r"(hi) : "memory");
                asm volatile("st.shared::cluster.u32 [%0], %1;"
                             :: "r"(dA[r] + off + 8192), "r"(lo) : "memory");
            }
        }

        // ---- single cluster barrier per step ----
        asm volatile("barrier.cluster.arrive.aligned;" ::: "memory");
        asm volatile("barrier.cluster.wait.aligned;" ::: "memory");
    }
}

// ---------------- BN stats ----------------
__global__ __launch_bounds__(256) void k_stats() {
    int ch = threadIdx.x;
    size_t r0 = (size_t)blockIdx.x * 256;
    const float* p = g_H2 + r0 * H_ + ch;
    float s = 0.f, s2 = 0.f;
    for (int r = 0; r < 256; r++) {
        float v = p[(size_t)r * H_];
        s += v;
        s2 = fmaf(v, v, s2);
    }
    g_part[(size_t)blockIdx.x * 512 + ch] = s;
    g_part[(size_t)blockIdx.x * 512 + 256 + ch] = s2;
}

__global__ __launch_bounds__(512) void k_stats_final() {
    int i = threadIdx.x;
    float acc = 0.f;
    for (int b = 0; b < 512; b++) acc += g_part[(size_t)b * 512 + i];
    g_bnsum[i] = acc;
}

// ---------------- normalize + hardtanh + temporal mean ----------------
__global__ __launch_bounds__(256) void k_summary(const float* __restrict__ gamma,
                                                 const float* __restrict__ beta) {
    int ch = threadIdx.x;
    int b = blockIdx.x;
    const float inv_bt = 1.0f / (float)BT_;
    float mean = g_bnsum[ch] * inv_bt;
    float var = g_bnsum[256 + ch] * inv_bt - mean * mean;
    float rstd = rsqrtf(var + EPS_);
    float scale = gamma[ch] * rstd;
    float shift = beta[ch] - mean * scale;

    const float* p = g_H2 + (size_t)b * T_ * H_ + ch;
    float acc = 0.f;
    for (int t = 0; t < T_; t++) {
        float v = fmaf(p[(size_t)t * H_], scale, shift);
        v = fminf(2.0f, fmaxf(-2.0f, v));
        acc += v;
    }
    g_sum[b * H_ + ch] = acc * (1.0f / (float)T_);
}

// ---------------- final FC ----------------
__global__ __launch_bounds__(128) void k_fc(const float* __restrict__ fc_w,
                                            const float* __restrict__ fc_b,
                                            float* __restrict__ out) {
    __shared__ float s[256];
    int o = threadIdx.x;
    int b = blockIdx.x;
    s[o] = g_sum[b * H_ + o];
    s[o + 128] = g_sum[b * H_ + o + 128];
    __syncthreads();
    float acc = fc_b[o];
    const float* w = fc_w + (size_t)o * H_;
#pragma unroll 8
    for (int ch = 0; ch < H_; ch++) acc = fmaf(s[ch], w[ch], acc);
    out[b * OUT_ + o] = acc;
}

// ---------------- launch ----------------
extern "C" void kernel_launch(void* const* d_in, const int* in_sizes, int n_in,
                              void* d_out, int out_size) {
    const float* x     = (const float*)d_in[0];
    const float* w_ih1 = (const float*)d_in[1];
    const float* w_hh1 = (const float*)d_in[2];
    const float* b_ih1 = (const float*)d_in[3];
    const float* b_hh1 = (const float*)d_in[4];
    const float* w_ih2 = (const float*)d_in[5];
    const float* w_hh2 = (const float*)d_in[6];
    const float* b_ih2 = (const float*)d_in[7];
    const float* b_hh2 = (const float*)d_in[8];
    const float* gamma = (const float*)d_in[9];
    const float* beta  = (const float*)d_in[10];
    const float* fc_w  = (const float*)d_in[11];
    const float* fc_b  = (const float*)d_in[12];
    float* out = (float*)d_out;

    cudaFuncSetAttribute(k_recur<1>, cudaFuncAttributeMaxDynamicSharedMemorySize, SMEM_REC);
    cudaFuncSetAttribute(k_recur<2>, cudaFuncAttributeMaxDynamicSharedMemorySize, SMEM_REC);

    dim3 mma_grid(G3_ / 64, BT_ / 128);      // (12, 1024)
    dim3 rec_grid(16, 4);                    // 16 clusters x 4 feature CTAs

    k_mma<128, 0><<<mma_grid, 256>>>(x, w_ih1, b_ih1);
    k_recur<1><<<rec_grid, 512, SMEM_REC>>>(w_hh1, b_hh1);
    k_mma<256, 1><<<mma_grid, 256>>>(nullptr, w_ih2, b_ih2);
    k_recur<2><<<rec_grid, 512, SMEM_REC>>>(w_hh2, b_hh2);

    k_stats<<<512, 256>>>();
    k_stats_final<<<1, 512>>>();
    k_summary<<<B_, 256>>>(gamma, beta);
    k_fc<<<B_, 128>>>(fc_w, fc_b, out);
}